// round 2
// baseline (speedup 1.0000x reference)
#include <cuda_runtime.h>
#include <cuda_bf16.h>
#include <cstdint>

#define BATCH 4096
#define DIM 512
#define TWOB 8192
#define INV_TEMP 10.0f

// ---------------- scratch (no allocations allowed) ----------------
__device__ __nv_bfloat16 g_z[(size_t)TWOB * DIM];   // normalized rows, bf16 [8192,512]
__device__ float g_pos[BATCH];                      // cos(n1_i, n2_i)
__device__ float g_rowsum[TWOB];                    // sum_{j!=i} exp(cos_ij/T)

// ---------------- helpers ----------------
__device__ __forceinline__ uint32_t smem_u32(const void* p) {
    uint32_t a;
    asm("{ .reg .u64 t; cvta.to.shared.u64 t, %1; cvt.u32.u64 %0, t; }" : "=r"(a) : "l"(p));
    return a;
}
__device__ __forceinline__ void cp16(uint32_t s, const void* g) {
    asm volatile("cp.async.cg.shared.global [%0], [%1], 16;" :: "r"(s), "l"(g) : "memory");
}
__device__ __forceinline__ void ldm_x4(uint32_t& r0, uint32_t& r1, uint32_t& r2, uint32_t& r3,
                                       uint32_t addr) {
    asm volatile("ldmatrix.sync.aligned.m8n8.x4.shared.b16 {%0,%1,%2,%3}, [%4];"
                 : "=r"(r0), "=r"(r1), "=r"(r2), "=r"(r3) : "r"(addr));
}
__device__ __forceinline__ void mma_16816(float* d, const uint32_t* a, const uint32_t* b) {
    asm volatile(
        "mma.sync.aligned.m16n8k16.row.col.f32.bf16.bf16.f32 "
        "{%0,%1,%2,%3}, {%4,%5,%6,%7}, {%8,%9}, {%0,%1,%2,%3};"
        : "+f"(d[0]), "+f"(d[1]), "+f"(d[2]), "+f"(d[3])
        : "r"(a[0]), "r"(a[1]), "r"(a[2]), "r"(a[3]), "r"(b[0]), "r"(b[1]));
}

// tile geometry
#define BM 128
#define BN 128
#define BK 32
#define NSTEPS (DIM / BK)    // 16
#define TILE_BYTES (BM * BK * 2)   // 8192 per operand tile
#define STAGE_BYTES (2 * TILE_BYTES)

// swizzled byte offset inside a [rows x 32cols bf16] tile (64B per row, 4 x 16B chunks)
__device__ __forceinline__ uint32_t swz(int row, int chunk) {
    return (uint32_t)(row * 64 + ((chunk ^ ((row >> 1) & 3)) << 4));
}

// ============ Kernel A: L2-normalize rows, positives, zero rowsums ============
__global__ void __launch_bounds__(128) k_norm(const float* __restrict__ p1,
                                              const float* __restrict__ p2) {
    const int i = blockIdx.x;
    const int t = threadIdx.x, w = t >> 5, l = t & 31;
    __shared__ float red[8];

    float4 a = ((const float4*)(p1 + (size_t)i * DIM))[t];
    float4 b = ((const float4*)(p2 + (size_t)i * DIM))[t];
    float sa = a.x * a.x + a.y * a.y + a.z * a.z + a.w * a.w;
    float sb = b.x * b.x + b.y * b.y + b.z * b.z + b.w * b.w;
#pragma unroll
    for (int o = 16; o; o >>= 1) {
        sa += __shfl_xor_sync(0xffffffffu, sa, o);
        sb += __shfl_xor_sync(0xffffffffu, sb, o);
    }
    if (!l) { red[w] = sa; red[4 + w] = sb; }
    __syncthreads();
    sa = red[0] + red[1] + red[2] + red[3];
    sb = red[4] + red[5] + red[6] + red[7];
    const float ra = rsqrtf(fmaxf(sa, 1e-24f));
    const float rb = rsqrtf(fmaxf(sb, 1e-24f));
    float4 na = make_float4(a.x * ra, a.y * ra, a.z * ra, a.w * ra);
    float4 nb = make_float4(b.x * rb, b.y * rb, b.z * rb, b.w * rb);
    float dp = na.x * nb.x + na.y * nb.y + na.z * nb.z + na.w * nb.w;
#pragma unroll
    for (int o = 16; o; o >>= 1) dp += __shfl_xor_sync(0xffffffffu, dp, o);
    __syncthreads();
    if (!l) red[w] = dp;
    __syncthreads();
    if (!t) {
        g_pos[i] = red[0] + red[1] + red[2] + red[3];
        g_rowsum[i] = 0.f;
        g_rowsum[BATCH + i] = 0.f;
    }
    __nv_bfloat162* z1 = (__nv_bfloat162*)(g_z + (size_t)i * DIM);
    __nv_bfloat162* z2 = (__nv_bfloat162*)(g_z + (size_t)(BATCH + i) * DIM);
    z1[2 * t]     = __floats2bfloat162_rn(na.x, na.y);
    z1[2 * t + 1] = __floats2bfloat162_rn(na.z, na.w);
    z2[2 * t]     = __floats2bfloat162_rn(nb.x, nb.y);
    z2[2 * t + 1] = __floats2bfloat162_rn(nb.z, nb.w);
}

// ============ Kernel B: fused 128x128 GEMM (HMMA) + exp + rowsum ============
__global__ void __launch_bounds__(256) k_sim() {
    __shared__ __align__(128) char smem[2 * STAGE_BYTES];  // 32 KB, 2 stages
    const uint32_t sbase = smem_u32(smem);

    const int tid = threadIdx.x;
    const int lane = tid & 31;
    const int wid = tid >> 5;
    const int warp_m = wid & 3;        // 4 warps along M (32 rows each)
    const int warp_n = wid >> 2;       // 2 warps along N (64 cols each)
    const int ti = blockIdx.y, tj = blockIdx.x;

    const __nv_bfloat16* za = g_z + (size_t)ti * BM * DIM;
    const __nv_bfloat16* zb = g_z + (size_t)tj * BN * DIM;

    // per-thread load slots: 4 x 16B per stage (A tile + B tile = 1024 chunks / 256 thr)
    // linear chunk id = it*256 + tid; tile = id>>9 (0=A,1=B); idx = id&511; row=idx>>2; ch=idx&3
    auto load_stage = [&](int kc, int st) {
        const uint32_t sA = sbase + st * STAGE_BYTES;
        const uint32_t sB = sA + TILE_BYTES;
#pragma unroll
        for (int it = 0; it < 4; it++) {
            int id = it * 256 + tid;
            int tile = id >> 9;
            int idx = id & 511;
            int row = idx >> 2, ch = idx & 3;
            const __nv_bfloat16* g = (tile ? zb : za) + (size_t)row * DIM + kc * BK + ch * 8;
            cp16((tile ? sB : sA) + swz(row, ch), g);
        }
        asm volatile("cp.async.commit_group;" ::: "memory");
    };

    float acc[2][8][4];
#pragma unroll
    for (int mt = 0; mt < 2; mt++)
#pragma unroll
        for (int nt = 0; nt < 8; nt++)
#pragma unroll
            for (int c = 0; c < 4; c++) acc[mt][nt][c] = 0.f;

    load_stage(0, 0);
    load_stage(1, 1);

    // precompute ldmatrix lane address components
    // A: row = warp_m*32 + mt*16 + (lane%16); chunk = ks*2 + (lane/16)
    const int a_row = warp_m * 32 + (lane & 15);
    const int a_chsel = lane >> 4;                 // 0/1 -> k-low / k-high
    // B: row = warp_n*64 + p*16 + (lane&7) + ((lane>>4)<<3); chunk = ks*2 + ((lane>>3)&1)
    const int b_row = warp_n * 64 + (lane & 7) + ((lane >> 4) << 3);
    const int b_chsel = (lane >> 3) & 1;

    for (int kc = 0; kc < NSTEPS; kc++) {
        if (kc == NSTEPS - 1) asm volatile("cp.async.wait_group 0;" ::: "memory");
        else                  asm volatile("cp.async.wait_group 1;" ::: "memory");
        __syncthreads();

        const uint32_t sA = sbase + (kc & 1) * STAGE_BYTES;
        const uint32_t sB = sA + TILE_BYTES;

#pragma unroll
        for (int ks = 0; ks < 2; ks++) {          // two k16 steps per 32-chunk
            uint32_t a[2][4];
#pragma unroll
            for (int mt = 0; mt < 2; mt++) {
                int row = a_row + mt * 16;
                ldm_x4(a[mt][0], a[mt][1], a[mt][2], a[mt][3],
                       sA + swz(row, ks * 2 + a_chsel));
            }
            uint32_t b[8][2];
#pragma unroll
            for (int p = 0; p < 4; p++) {
                int row = b_row + p * 16;
                uint32_t r0, r1, r2, r3;
                ldm_x4(r0, r1, r2, r3, sB + swz(row, ks * 2 + b_chsel));
                b[p * 2][0] = r0; b[p * 2][1] = r1;
                b[p * 2 + 1][0] = r2; b[p * 2 + 1][1] = r3;
            }
#pragma unroll
            for (int mt = 0; mt < 2; mt++)
#pragma unroll
                for (int nt = 0; nt < 8; nt++)
                    mma_16816(acc[mt][nt], a[mt], b[nt]);
        }

        __syncthreads();
        if (kc + 2 < NSTEPS) load_stage(kc + 2, kc & 1);
    }

    // ---------------- epilogue: exp + per-row sums ----------------
    // fragment rows: r = lane>>2 (+8 for c2,c3); cols: 2*(lane&3) + (c&1)
    const int row0 = ti * BM + warp_m * 32 + (lane >> 2);
    const int col0 = tj * BN + warp_n * 64 + (lane & 3) * 2;
    float rs[2][2] = {{0.f, 0.f}, {0.f, 0.f}};   // [mt][rowhalf]
#pragma unroll
    for (int mt = 0; mt < 2; mt++) {
#pragma unroll
        for (int nt = 0; nt < 8; nt++) {
#pragma unroll
            for (int c = 0; c < 4; c++) {
                int grow = row0 + mt * 16 + (c >> 1) * 8;
                int gcol = col0 + nt * 8 + (c & 1);
                float e = __expf(acc[mt][nt][c] * INV_TEMP);
                rs[mt][c >> 1] += (grow == gcol) ? 0.f : e;
            }
        }
    }
    // quad reduce (lanes sharing a row differ only in lane&3)
#pragma unroll
    for (int o = 1; o <= 2; o <<= 1) {
#pragma unroll
        for (int mt = 0; mt < 2; mt++)
#pragma unroll
            for (int h = 0; h < 2; h++)
                rs[mt][h] += __shfl_xor_sync(0xffffffffu, rs[mt][h], o);
    }
    if ((lane & 3) == 0) {
#pragma unroll
        for (int mt = 0; mt < 2; mt++)
#pragma unroll
            for (int h = 0; h < 2; h++)
                atomicAdd(&g_rowsum[row0 + mt * 16 + h * 8], rs[mt][h]);
    }
}

// ============ Kernel C: final reduction ============
__global__ void __launch_bounds__(1024) k_red(float* __restrict__ out) {
    __shared__ float sh[1024];
    const int t = threadIdx.x;
    float s = 0.f;
    for (int i = t; i < TWOB; i += 1024) s += logf(g_rowsum[i]);
    float p = 0.f;
    for (int i = t; i < BATCH; i += 1024) p += g_pos[i];
    sh[t] = s - 2.f * INV_TEMP * p;   // sum(lse) - sum(positive logits)
    __syncthreads();
    for (int o = 512; o; o >>= 1) {
        if (t < o) sh[t] += sh[t + o];
        __syncthreads();
    }
    if (!t) out[0] = sh[0] / (float)TWOB;
}

extern "C" void kernel_launch(void* const* d_in, const int* in_sizes, int n_in,
                              void* d_out, int out_size) {
    const float* p1 = (const float*)d_in[0];
    const float* p2 = (const float*)d_in[1];
    k_norm<<<BATCH, 128>>>(p1, p2);
    k_sim<<<dim3(TWOB / BN, TWOB / BM), 256>>>();
    k_red<<<1, 1024>>>((float*)d_out);
}

// round 3
// speedup vs baseline: 1.5063x; 1.5063x over previous
#include <cuda_runtime.h>
#include <cuda_bf16.h>
#include <cstdint>

#define BATCH 4096
#define DIM 512
#define TWOB 8192
#define INV_TEMP 10.0f

// ---------------- scratch (no allocations allowed) ----------------
__device__ __nv_bfloat16 g_z[(size_t)TWOB * DIM];   // normalized rows, bf16 [8192,512]
__device__ float g_pos[BATCH];                      // cos(n1_i, n2_i)
__device__ float g_rowsum[TWOB];                    // sum_{j!=i} exp(cos_ij/T)

// ---------------- helpers ----------------
__device__ __forceinline__ uint32_t smem_u32(const void* p) {
    uint32_t a;
    asm("{ .reg .u64 t; cvta.to.shared.u64 t, %1; cvt.u32.u64 %0, t; }" : "=r"(a) : "l"(p));
    return a;
}
__device__ __forceinline__ void cp16(uint32_t s, const void* g) {
    asm volatile("cp.async.cg.shared.global [%0], [%1], 16;" :: "r"(s), "l"(g) : "memory");
}
__device__ __forceinline__ void ldm_x4(uint32_t& r0, uint32_t& r1, uint32_t& r2, uint32_t& r3,
                                       uint32_t addr) {
    asm volatile("ldmatrix.sync.aligned.m8n8.x4.shared.b16 {%0,%1,%2,%3}, [%4];"
                 : "=r"(r0), "=r"(r1), "=r"(r2), "=r"(r3) : "r"(addr));
}
__device__ __forceinline__ void mma_16816(float* d, const uint32_t* a, const uint32_t* b) {
    asm volatile(
        "mma.sync.aligned.m16n8k16.row.col.f32.bf16.bf16.f32 "
        "{%0,%1,%2,%3}, {%4,%5,%6,%7}, {%8,%9}, {%0,%1,%2,%3};"
        : "+f"(d[0]), "+f"(d[1]), "+f"(d[2]), "+f"(d[3])
        : "r"(a[0]), "r"(a[1]), "r"(a[2]), "r"(a[3]), "r"(b[0]), "r"(b[1]));
}

// tile geometry
#define BM 128
#define BN 128
#define BK 32
#define NSTEPS (DIM / BK)          // 16
#define NT (TWOB / BM)             // 64 tile-rows
#define NTILES (NT * (NT + 1) / 2) // 2080 upper-triangle tiles
#define TILE_BYTES (BM * BK * 2)   // 8192 per operand tile
#define STAGE_BYTES (2 * TILE_BYTES)
#define NSTAGE 3

// swizzled byte offset inside a [rows x 32cols bf16] tile (64B per row, 4 x 16B chunks)
__device__ __forceinline__ uint32_t swz(int row, int chunk) {
    return (uint32_t)(row * 64 + ((chunk ^ ((row >> 1) & 3)) << 4));
}

// ============ Kernel A: L2-normalize rows, positives, zero rowsums ============
__global__ void __launch_bounds__(128) k_norm(const float* __restrict__ p1,
                                              const float* __restrict__ p2) {
    const int i = blockIdx.x;
    const int t = threadIdx.x, w = t >> 5, l = t & 31;
    __shared__ float red[8];

    float4 a = ((const float4*)(p1 + (size_t)i * DIM))[t];
    float4 b = ((const float4*)(p2 + (size_t)i * DIM))[t];
    float sa = a.x * a.x + a.y * a.y + a.z * a.z + a.w * a.w;
    float sb = b.x * b.x + b.y * b.y + b.z * b.z + b.w * b.w;
#pragma unroll
    for (int o = 16; o; o >>= 1) {
        sa += __shfl_xor_sync(0xffffffffu, sa, o);
        sb += __shfl_xor_sync(0xffffffffu, sb, o);
    }
    if (!l) { red[w] = sa; red[4 + w] = sb; }
    __syncthreads();
    sa = red[0] + red[1] + red[2] + red[3];
    sb = red[4] + red[5] + red[6] + red[7];
    const float ra = rsqrtf(fmaxf(sa, 1e-24f));
    const float rb = rsqrtf(fmaxf(sb, 1e-24f));
    float4 na = make_float4(a.x * ra, a.y * ra, a.z * ra, a.w * ra);
    float4 nb = make_float4(b.x * rb, b.y * rb, b.z * rb, b.w * rb);
    float dp = na.x * nb.x + na.y * nb.y + na.z * nb.z + na.w * nb.w;
#pragma unroll
    for (int o = 16; o; o >>= 1) dp += __shfl_xor_sync(0xffffffffu, dp, o);
    __syncthreads();
    if (!l) red[w] = dp;
    __syncthreads();
    if (!t) {
        g_pos[i] = red[0] + red[1] + red[2] + red[3];
        g_rowsum[i] = 0.f;
        g_rowsum[BATCH + i] = 0.f;
    }
    __nv_bfloat162* z1 = (__nv_bfloat162*)(g_z + (size_t)i * DIM);
    __nv_bfloat162* z2 = (__nv_bfloat162*)(g_z + (size_t)(BATCH + i) * DIM);
    z1[2 * t]     = __floats2bfloat162_rn(na.x, na.y);
    z1[2 * t + 1] = __floats2bfloat162_rn(na.z, na.w);
    z2[2 * t]     = __floats2bfloat162_rn(nb.x, nb.y);
    z2[2 * t + 1] = __floats2bfloat162_rn(nb.z, nb.w);
}

// ============ Kernel B: upper-triangle fused GEMM (HMMA) + exp + row/col sums ============
__global__ void __launch_bounds__(256) k_sim() {
    __shared__ __align__(128) char smem[NSTAGE * STAGE_BYTES];  // 48 KB, 3 stages
    const uint32_t sbase = smem_u32(smem);

    const int tid = threadIdx.x;
    const int lane = tid & 31;
    const int wid = tid >> 5;
    const int warp_m = wid & 3;        // 4 warps along M (32 rows each)
    const int warp_n = wid >> 2;       // 2 warps along N (64 cols each)

    // map linear block id -> upper-triangle tile (ti <= tj)
    const int bid = blockIdx.x;
    auto offs = [](int t) { return t * NT - (t * (t - 1)) / 2; };
    int ti = (int)((2.f * NT + 1.f - sqrtf((2.f * NT + 1.f) * (2.f * NT + 1.f) - 8.f * bid)) * 0.5f);
    if (ti < 0) ti = 0;
    if (ti > NT - 1) ti = NT - 1;
    while (offs(ti + 1) <= bid) ti++;
    while (offs(ti) > bid) ti--;
    const int tj = ti + (bid - offs(ti));
    const bool diag = (ti == tj);

    const __nv_bfloat16* za = g_z + (size_t)ti * BM * DIM;
    const __nv_bfloat16* zb = g_z + (size_t)tj * BN * DIM;

    // per-thread load slots: 4 x 16B per stage (A tile + B tile = 1024 chunks / 256 thr)
    auto load_stage = [&](int kc) {
        const int st = kc % NSTAGE;
        const uint32_t sA = sbase + st * STAGE_BYTES;
        const uint32_t sB = sA + TILE_BYTES;
#pragma unroll
        for (int it = 0; it < 4; it++) {
            int id = it * 256 + tid;
            int tile = id >> 9;
            int idx = id & 511;
            int row = idx >> 2, ch = idx & 3;
            const __nv_bfloat16* g = (tile ? zb : za) + (size_t)row * DIM + kc * BK + ch * 8;
            cp16((tile ? sB : sA) + swz(row, ch), g);
        }
        asm volatile("cp.async.commit_group;" ::: "memory");
    };

    float acc[2][8][4];
#pragma unroll
    for (int mt = 0; mt < 2; mt++)
#pragma unroll
        for (int nt = 0; nt < 8; nt++)
#pragma unroll
            for (int c = 0; c < 4; c++) acc[mt][nt][c] = 0.f;

    load_stage(0);
    load_stage(1);

    // ldmatrix lane address components
    const int a_row = warp_m * 32 + (lane & 15);
    const int a_chsel = lane >> 4;
    const int b_row = warp_n * 64 + (lane & 7) + ((lane >> 4) << 3);
    const int b_chsel = (lane >> 3) & 1;

    for (int kc = 0; kc < NSTEPS; kc++) {
        asm volatile("cp.async.wait_group 1;" ::: "memory");
        __syncthreads();
        if (kc + NSTAGE - 1 < NSTEPS) load_stage(kc + NSTAGE - 1);  // into buffer freed last iter

        const uint32_t sA = sbase + (kc % NSTAGE) * STAGE_BYTES;
        const uint32_t sB = sA + TILE_BYTES;

#pragma unroll
        for (int ks = 0; ks < 2; ks++) {          // two k16 steps per 32-chunk
            uint32_t a[2][4];
#pragma unroll
            for (int mt = 0; mt < 2; mt++) {
                int row = a_row + mt * 16;
                ldm_x4(a[mt][0], a[mt][1], a[mt][2], a[mt][3],
                       sA + swz(row, ks * 2 + a_chsel));
            }
            uint32_t b[8][2];
#pragma unroll
            for (int p = 0; p < 4; p++) {
                int row = b_row + p * 16;
                uint32_t r0, r1, r2, r3;
                ldm_x4(r0, r1, r2, r3, sB + swz(row, ks * 2 + b_chsel));
                b[p * 2][0] = r0; b[p * 2][1] = r1;
                b[p * 2 + 1][0] = r2; b[p * 2 + 1][1] = r3;
            }
#pragma unroll
            for (int mt = 0; mt < 2; mt++)
#pragma unroll
                for (int nt = 0; nt < 8; nt++)
                    mma_16816(acc[mt][nt], a[mt], b[nt]);
        }
    }

    // ---------------- epilogue: exp + per-row (and per-col) sums ----------------
    const int row0 = ti * BM + warp_m * 32 + (lane >> 2);
    const int col0 = tj * BN + warp_n * 64 + (lane & 3) * 2;
    float rs[2][2] = {{0.f, 0.f}, {0.f, 0.f}};   // [mt][rowhalf]

    if (diag) {
        // tile on the diagonal: rows == cols block; mask self-similarity
#pragma unroll
        for (int mt = 0; mt < 2; mt++)
#pragma unroll
            for (int nt = 0; nt < 8; nt++)
#pragma unroll
                for (int c = 0; c < 4; c++) {
                    int grow = row0 + mt * 16 + (c >> 1) * 8;
                    int gcol = col0 + nt * 8 + (c & 1);
                    float e = __expf(acc[mt][nt][c] * INV_TEMP);
                    rs[mt][c >> 1] += (grow == gcol) ? 0.f : e;
                }
    } else {
        // off-diagonal: accumulate row sums AND column sums (symmetry)
        float cs[8][2];
#pragma unroll
        for (int nt = 0; nt < 8; nt++) { cs[nt][0] = 0.f; cs[nt][1] = 0.f; }
#pragma unroll
        for (int mt = 0; mt < 2; mt++)
#pragma unroll
            for (int nt = 0; nt < 8; nt++)
#pragma unroll
                for (int c = 0; c < 4; c++) {
                    float e = __expf(acc[mt][nt][c] * INV_TEMP);
                    rs[mt][c >> 1] += e;
                    cs[nt][c & 1] += e;
                }
        // reduce column sums across the 8 row-groups in the warp (lane bits 2..4)
#pragma unroll
        for (int o = 4; o <= 16; o <<= 1)
#pragma unroll
            for (int nt = 0; nt < 8; nt++) {
                cs[nt][0] += __shfl_xor_sync(0xffffffffu, cs[nt][0], o);
                cs[nt][1] += __shfl_xor_sync(0xffffffffu, cs[nt][1], o);
            }
        if (lane < 4) {
            const int cbase = tj * BN + warp_n * 64 + lane * 2;
#pragma unroll
            for (int nt = 0; nt < 8; nt++) {
                atomicAdd(&g_rowsum[cbase + nt * 8],     cs[nt][0]);
                atomicAdd(&g_rowsum[cbase + nt * 8 + 1], cs[nt][1]);
            }
        }
    }

    // row-sum quad reduce (lanes sharing a row differ only in lane&3)
#pragma unroll
    for (int o = 1; o <= 2; o <<= 1)
#pragma unroll
        for (int mt = 0; mt < 2; mt++)
#pragma unroll
            for (int h = 0; h < 2; h++)
                rs[mt][h] += __shfl_xor_sync(0xffffffffu, rs[mt][h], o);
    if ((lane & 3) == 0) {
#pragma unroll
        for (int mt = 0; mt < 2; mt++)
#pragma unroll
            for (int h = 0; h < 2; h++)
                atomicAdd(&g_rowsum[row0 + mt * 16 + h * 8], rs[mt][h]);
    }
}

// ============ Kernel C: final reduction ============
__global__ void __launch_bounds__(1024) k_red(float* __restrict__ out) {
    __shared__ float sh[1024];
    const int t = threadIdx.x;
    float s = 0.f;
    for (int i = t; i < TWOB; i += 1024) s += logf(g_rowsum[i]);
    float p = 0.f;
    for (int i = t; i < BATCH; i += 1024) p += g_pos[i];
    sh[t] = s - 2.f * INV_TEMP * p;   // sum(lse) - sum(positive logits)
    __syncthreads();
    for (int o = 512; o; o >>= 1) {
        if (t < o) sh[t] += sh[t + o];
        __syncthreads();
    }
    if (!t) out[0] = sh[0] / (float)TWOB;
}

extern "C" void kernel_launch(void* const* d_in, const int* in_sizes, int n_in,
                              void* d_out, int out_size) {
    const float* p1 = (const float*)d_in[0];
    const float* p2 = (const float*)d_in[1];
    k_norm<<<BATCH, 128>>>(p1, p2);
    k_sim<<<NTILES, 256>>>();
    k_red<<<1, 1024>>>((float*)d_out);
}

// round 4
// speedup vs baseline: 1.7002x; 1.1287x over previous
#include <cuda_runtime.h>
#include <cuda_bf16.h>
#include <cstdint>

#define BATCH 4096
#define DIM 512
#define TWOB 8192
#define INV_TEMP 10.0f

// ---------------- scratch (no allocations allowed) ----------------
__device__ __nv_bfloat16 g_z[(size_t)TWOB * DIM];   // normalized rows, bf16 [8192,512]
__device__ float g_pos[BATCH];                      // cos(n1_i, n2_i)
__device__ float g_rowsum[TWOB];                    // sum_{j!=i} exp(cos_ij/T)

// ---------------- helpers ----------------
__device__ __forceinline__ uint32_t smem_u32(const void* p) {
    uint32_t a;
    asm("{ .reg .u64 t; cvta.to.shared.u64 t, %1; cvt.u32.u64 %0, t; }" : "=r"(a) : "l"(p));
    return a;
}
__device__ __forceinline__ void cp16(uint32_t s, const void* g) {
    asm volatile("cp.async.cg.shared.global [%0], [%1], 16;" :: "r"(s), "l"(g) : "memory");
}
__device__ __forceinline__ void ldm_x4(uint32_t& r0, uint32_t& r1, uint32_t& r2, uint32_t& r3,
                                       uint32_t addr) {
    asm volatile("ldmatrix.sync.aligned.m8n8.x4.shared.b16 {%0,%1,%2,%3}, [%4];"
                 : "=r"(r0), "=r"(r1), "=r"(r2), "=r"(r3) : "r"(addr));
}
__device__ __forceinline__ void mma_16816(float* d, const uint32_t* a, const uint32_t* b) {
    asm volatile(
        "mma.sync.aligned.m16n8k16.row.col.f32.bf16.bf16.f32 "
        "{%0,%1,%2,%3}, {%4,%5,%6,%7}, {%8,%9}, {%0,%1,%2,%3};"
        : "+f"(d[0]), "+f"(d[1]), "+f"(d[2]), "+f"(d[3])
        : "r"(a[0]), "r"(a[1]), "r"(a[2]), "r"(a[3]), "r"(b[0]), "r"(b[1]));
}

// tile geometry
#define BM 128
#define BN 128
#define BK 32
#define NSTEPS (DIM / BK)          // 16
#define NT (TWOB / BM)             // 64 tile-rows
#define NTILES (NT * (NT + 1) / 2) // 2080 upper-triangle tiles
#define TILE_BYTES (BM * BK * 2)   // 8192 per operand tile
#define STAGE_BYTES (2 * TILE_BYTES)
#define NSTAGE 3

// swizzled byte offset inside a [rows x 32cols bf16] tile (64B per row, 4 x 16B chunks)
__device__ __forceinline__ uint32_t swz(int row, int chunk) {
    return (uint32_t)(row * 64 + ((chunk ^ ((row >> 1) & 3)) << 4));
}

// ============ Kernel A: L2-normalize rows, positives, zero rowsums ============
__global__ void __launch_bounds__(128) k_norm(const float* __restrict__ p1,
                                              const float* __restrict__ p2) {
    const int i = blockIdx.x;
    const int t = threadIdx.x, w = t >> 5, l = t & 31;
    __shared__ float red[8];

    float4 a = ((const float4*)(p1 + (size_t)i * DIM))[t];
    float4 b = ((const float4*)(p2 + (size_t)i * DIM))[t];
    float sa = a.x * a.x + a.y * a.y + a.z * a.z + a.w * a.w;
    float sb = b.x * b.x + b.y * b.y + b.z * b.z + b.w * b.w;
#pragma unroll
    for (int o = 16; o; o >>= 1) {
        sa += __shfl_xor_sync(0xffffffffu, sa, o);
        sb += __shfl_xor_sync(0xffffffffu, sb, o);
    }
    if (!l) { red[w] = sa; red[4 + w] = sb; }
    __syncthreads();
    sa = red[0] + red[1] + red[2] + red[3];
    sb = red[4] + red[5] + red[6] + red[7];
    const float ra = rsqrtf(fmaxf(sa, 1e-24f));
    const float rb = rsqrtf(fmaxf(sb, 1e-24f));
    float4 na = make_float4(a.x * ra, a.y * ra, a.z * ra, a.w * ra);
    float4 nb = make_float4(b.x * rb, b.y * rb, b.z * rb, b.w * rb);
    float dp = na.x * nb.x + na.y * nb.y + na.z * nb.z + na.w * nb.w;
#pragma unroll
    for (int o = 16; o; o >>= 1) dp += __shfl_xor_sync(0xffffffffu, dp, o);
    __syncthreads();
    if (!l) red[w] = dp;
    __syncthreads();
    if (!t) {
        g_pos[i] = red[0] + red[1] + red[2] + red[3];
        g_rowsum[i] = 0.f;
        g_rowsum[BATCH + i] = 0.f;
    }
    __nv_bfloat162* z1 = (__nv_bfloat162*)(g_z + (size_t)i * DIM);
    __nv_bfloat162* z2 = (__nv_bfloat162*)(g_z + (size_t)(BATCH + i) * DIM);
    z1[2 * t]     = __floats2bfloat162_rn(na.x, na.y);
    z1[2 * t + 1] = __floats2bfloat162_rn(na.z, na.w);
    z2[2 * t]     = __floats2bfloat162_rn(nb.x, nb.y);
    z2[2 * t + 1] = __floats2bfloat162_rn(nb.z, nb.w);
}

// ============ Kernel B: upper-triangle fused GEMM (HMMA) + exp + row/col sums ============
// 2 CTAs/SM: one CTA's prologue/epilogue overlaps the other's HMMA stream.
__global__ void __launch_bounds__(256, 2) k_sim() {
    __shared__ __align__(128) char smem[NSTAGE * STAGE_BYTES];  // 48 KB, 3 stages
    const uint32_t sbase = smem_u32(smem);

    const int tid = threadIdx.x;
    const int lane = tid & 31;
    const int wid = tid >> 5;
    const int warp_m = wid & 3;        // 4 warps along M (32 rows each)
    const int warp_n = wid >> 2;       // 2 warps along N (64 cols each)

    // map linear block id -> upper-triangle tile (ti <= tj)
    const int bid = blockIdx.x;
    auto offs = [](int t) { return t * NT - (t * (t - 1)) / 2; };
    int ti = (int)((2.f * NT + 1.f - sqrtf((2.f * NT + 1.f) * (2.f * NT + 1.f) - 8.f * bid)) * 0.5f);
    if (ti < 0) ti = 0;
    if (ti > NT - 1) ti = NT - 1;
    while (offs(ti + 1) <= bid) ti++;
    while (offs(ti) > bid) ti--;
    const int tj = ti + (bid - offs(ti));
    const bool diag = (ti == tj);

    const __nv_bfloat16* za = g_z + (size_t)ti * BM * DIM;
    const __nv_bfloat16* zb = g_z + (size_t)tj * BN * DIM;

    // per-thread load slots: 4 x 16B per stage (A tile + B tile = 1024 chunks / 256 thr)
    auto load_stage = [&](int kc) {
        const int st = kc % NSTAGE;
        const uint32_t sA = sbase + st * STAGE_BYTES;
        const uint32_t sB = sA + TILE_BYTES;
#pragma unroll
        for (int it = 0; it < 4; it++) {
            int id = it * 256 + tid;
            int tile = id >> 9;
            int idx = id & 511;
            int row = idx >> 2, ch = idx & 3;
            const __nv_bfloat16* g = (tile ? zb : za) + (size_t)row * DIM + kc * BK + ch * 8;
            cp16((tile ? sB : sA) + swz(row, ch), g);
        }
        asm volatile("cp.async.commit_group;" ::: "memory");
    };

    float acc[2][8][4];
#pragma unroll
    for (int mt = 0; mt < 2; mt++)
#pragma unroll
        for (int nt = 0; nt < 8; nt++)
#pragma unroll
            for (int c = 0; c < 4; c++) acc[mt][nt][c] = 0.f;

    load_stage(0);
    load_stage(1);

    // ldmatrix lane address components
    const int a_row = warp_m * 32 + (lane & 15);
    const int a_chsel = lane >> 4;
    const int b_row = warp_n * 64 + (lane & 7) + ((lane >> 4) << 3);
    const int b_chsel = (lane >> 3) & 1;

    for (int kc = 0; kc < NSTEPS; kc++) {
        asm volatile("cp.async.wait_group 1;" ::: "memory");
        __syncthreads();
        if (kc + NSTAGE - 1 < NSTEPS) load_stage(kc + NSTAGE - 1);  // into buffer freed last iter

        const uint32_t sA = sbase + (kc % NSTAGE) * STAGE_BYTES;
        const uint32_t sB = sA + TILE_BYTES;

#pragma unroll
        for (int ks = 0; ks < 2; ks++) {          // two k16 steps per 32-chunk
            uint32_t a[2][4];
#pragma unroll
            for (int mt = 0; mt < 2; mt++) {
                int row = a_row + mt * 16;
                ldm_x4(a[mt][0], a[mt][1], a[mt][2], a[mt][3],
                       sA + swz(row, ks * 2 + a_chsel));
            }
            // stream B fragments: load one ldm.x4 (two n8 frags), use, discard.
            // keeps only 4 B regs live -> fits 2-CTA/SM register budget.
#pragma unroll
            for (int p = 0; p < 4; p++) {
                int row = b_row + p * 16;
                uint32_t b[4];
                ldm_x4(b[0], b[1], b[2], b[3], sB + swz(row, ks * 2 + b_chsel));
#pragma unroll
                for (int mt = 0; mt < 2; mt++) {
                    mma_16816(acc[mt][p * 2],     a[mt], b);
                    mma_16816(acc[mt][p * 2 + 1], a[mt], b + 2);
                }
            }
        }
    }

    // ---------------- epilogue: exp + per-row (and per-col) sums ----------------
    const int row0 = ti * BM + warp_m * 32 + (lane >> 2);
    const int col0 = tj * BN + warp_n * 64 + (lane & 3) * 2;
    float rs[2][2] = {{0.f, 0.f}, {0.f, 0.f}};   // [mt][rowhalf]

    if (diag) {
        // tile on the diagonal: rows == cols block; mask self-similarity
#pragma unroll
        for (int mt = 0; mt < 2; mt++)
#pragma unroll
            for (int nt = 0; nt < 8; nt++)
#pragma unroll
                for (int c = 0; c < 4; c++) {
                    int grow = row0 + mt * 16 + (c >> 1) * 8;
                    int gcol = col0 + nt * 8 + (c & 1);
                    float e = __expf(acc[mt][nt][c] * INV_TEMP);
                    rs[mt][c >> 1] += (grow == gcol) ? 0.f : e;
                }
    } else {
        // off-diagonal: accumulate row sums AND column sums (symmetry)
        float cs[8][2];
#pragma unroll
        for (int nt = 0; nt < 8; nt++) { cs[nt][0] = 0.f; cs[nt][1] = 0.f; }
#pragma unroll
        for (int mt = 0; mt < 2; mt++)
#pragma unroll
            for (int nt = 0; nt < 8; nt++)
#pragma unroll
                for (int c = 0; c < 4; c++) {
                    float e = __expf(acc[mt][nt][c] * INV_TEMP);
                    rs[mt][c >> 1] += e;
                    cs[nt][c & 1] += e;
                }
        // reduce column sums across the 8 row-groups in the warp (lane bits 2..4)
#pragma unroll
        for (int o = 4; o <= 16; o <<= 1)
#pragma unroll
            for (int nt = 0; nt < 8; nt++) {
                cs[nt][0] += __shfl_xor_sync(0xffffffffu, cs[nt][0], o);
                cs[nt][1] += __shfl_xor_sync(0xffffffffu, cs[nt][1], o);
            }
        if (lane < 4) {
            const int cbase = tj * BN + warp_n * 64 + lane * 2;
#pragma unroll
            for (int nt = 0; nt < 8; nt++) {
                atomicAdd(&g_rowsum[cbase + nt * 8],     cs[nt][0]);
                atomicAdd(&g_rowsum[cbase + nt * 8 + 1], cs[nt][1]);
            }
        }
    }

    // row-sum quad reduce (lanes sharing a row differ only in lane&3)
#pragma unroll
    for (int o = 1; o <= 2; o <<= 1)
#pragma unroll
        for (int mt = 0; mt < 2; mt++)
#pragma unroll
            for (int h = 0; h < 2; h++)
                rs[mt][h] += __shfl_xor_sync(0xffffffffu, rs[mt][h], o);
    if ((lane & 3) == 0) {
#pragma unroll
        for (int mt = 0; mt < 2; mt++)
#pragma unroll
            for (int h = 0; h < 2; h++)
                atomicAdd(&g_rowsum[row0 + mt * 16 + h * 8], rs[mt][h]);
    }
}

// ============ Kernel C: final reduction ============
__global__ void __launch_bounds__(1024) k_red(float* __restrict__ out) {
    __shared__ float sh[1024];
    const int t = threadIdx.x;
    float s = 0.f;
    for (int i = t; i < TWOB; i += 1024) s += logf(g_rowsum[i]);
    float p = 0.f;
    for (int i = t; i < BATCH; i += 1024) p += g_pos[i];
    sh[t] = s - 2.f * INV_TEMP * p;   // sum(lse) - sum(positive logits)
    __syncthreads();
    for (int o = 512; o; o >>= 1) {
        if (t < o) sh[t] += sh[t + o];
        __syncthreads();
    }
    if (!t) out[0] = sh[0] / (float)TWOB;
}

extern "C" void kernel_launch(void* const* d_in, const int* in_sizes, int n_in,
                              void* d_out, int out_size) {
    const float* p1 = (const float*)d_in[0];
    const float* p2 = (const float*)d_in[1];
    k_norm<<<BATCH, 128>>>(p1, p2);
    k_sim<<<NTILES, 256>>>();
    k_red<<<1, 1024>>>((float*)d_out);
}

// round 5
// speedup vs baseline: 1.8389x; 1.0816x over previous
#include <cuda_runtime.h>
#include <cuda_bf16.h>
#include <cstdint>

#define BATCH 4096
#define DIM 512
#define TWOB 8192
#define INV_TEMP 10.0f

// ---------------- scratch (no allocations allowed) ----------------
__device__ __nv_bfloat16 g_z[(size_t)TWOB * DIM];   // normalized rows, bf16 [8192,512]
__device__ float g_pos[BATCH];                      // cos(n1_i, n2_i)
__device__ float g_rowsum[TWOB];                    // sum_{j!=i} exp(cos_ij/T)

// ---------------- helpers ----------------
__device__ __forceinline__ uint32_t smem_u32(const void* p) {
    uint32_t a;
    asm("{ .reg .u64 t; cvta.to.shared.u64 t, %1; cvt.u32.u64 %0, t; }" : "=r"(a) : "l"(p));
    return a;
}
__device__ __forceinline__ void cp16(uint32_t s, const void* g) {
    asm volatile("cp.async.cg.shared.global [%0], [%1], 16;" :: "r"(s), "l"(g) : "memory");
}
__device__ __forceinline__ void ldm_x4(uint32_t& r0, uint32_t& r1, uint32_t& r2, uint32_t& r3,
                                       uint32_t addr) {
    asm volatile("ldmatrix.sync.aligned.m8n8.x4.shared.b16 {%0,%1,%2,%3}, [%4];"
                 : "=r"(r0), "=r"(r1), "=r"(r2), "=r"(r3) : "r"(addr));
}
__device__ __forceinline__ void mma_16816(float* d, const uint32_t* a, const uint32_t* b) {
    asm volatile(
        "mma.sync.aligned.m16n8k16.row.col.f32.bf16.bf16.f32 "
        "{%0,%1,%2,%3}, {%4,%5,%6,%7}, {%8,%9}, {%0,%1,%2,%3};"
        : "+f"(d[0]), "+f"(d[1]), "+f"(d[2]), "+f"(d[3])
        : "r"(a[0]), "r"(a[1]), "r"(a[2]), "r"(a[3]), "r"(b[0]), "r"(b[1]));
}

// tile geometry
#define BM 128
#define BN 128
#define BK 32
#define NSTEPS (DIM / BK)          // 16
#define NT (TWOB / BM)             // 64 tile-rows
#define NTILES (NT * (NT + 1) / 2) // 2080 upper-triangle tiles
#define TILE_BYTES (BM * BK * 2)   // 8192 per operand tile
#define STAGE_BYTES (2 * TILE_BYTES)
#define NSTAGE 3

// swizzled byte offset inside a [rows x 32cols bf16] tile (64B per row, 4 x 16B chunks)
__device__ __forceinline__ uint32_t swz(int row, int chunk) {
    return (uint32_t)(row * 64 + ((chunk ^ ((row >> 1) & 3)) << 4));
}

// ============ Kernel A: L2-normalize rows, positives, zero rowsums ============
__global__ void __launch_bounds__(128) k_norm(const float* __restrict__ p1,
                                              const float* __restrict__ p2) {
    const int i = blockIdx.x;
    const int t = threadIdx.x, w = t >> 5, l = t & 31;
    __shared__ float red[8];

    float4 a = ((const float4*)(p1 + (size_t)i * DIM))[t];
    float4 b = ((const float4*)(p2 + (size_t)i * DIM))[t];
    float sa = a.x * a.x + a.y * a.y + a.z * a.z + a.w * a.w;
    float sb = b.x * b.x + b.y * b.y + b.z * b.z + b.w * b.w;
#pragma unroll
    for (int o = 16; o; o >>= 1) {
        sa += __shfl_xor_sync(0xffffffffu, sa, o);
        sb += __shfl_xor_sync(0xffffffffu, sb, o);
    }
    if (!l) { red[w] = sa; red[4 + w] = sb; }
    __syncthreads();
    sa = red[0] + red[1] + red[2] + red[3];
    sb = red[4] + red[5] + red[6] + red[7];
    const float ra = rsqrtf(fmaxf(sa, 1e-24f));
    const float rb = rsqrtf(fmaxf(sb, 1e-24f));
    float4 na = make_float4(a.x * ra, a.y * ra, a.z * ra, a.w * ra);
    float4 nb = make_float4(b.x * rb, b.y * rb, b.z * rb, b.w * rb);
    float dp = na.x * nb.x + na.y * nb.y + na.z * nb.z + na.w * nb.w;
#pragma unroll
    for (int o = 16; o; o >>= 1) dp += __shfl_xor_sync(0xffffffffu, dp, o);
    __syncthreads();
    if (!l) red[w] = dp;
    __syncthreads();
    if (!t) {
        g_pos[i] = red[0] + red[1] + red[2] + red[3];
        g_rowsum[i] = 0.f;
        g_rowsum[BATCH + i] = 0.f;
    }
    __nv_bfloat162* z1 = (__nv_bfloat162*)(g_z + (size_t)i * DIM);
    __nv_bfloat162* z2 = (__nv_bfloat162*)(g_z + (size_t)(BATCH + i) * DIM);
    z1[2 * t]     = __floats2bfloat162_rn(na.x, na.y);
    z1[2 * t + 1] = __floats2bfloat162_rn(na.z, na.w);
    z2[2 * t]     = __floats2bfloat162_rn(nb.x, nb.y);
    z2[2 * t + 1] = __floats2bfloat162_rn(nb.z, nb.w);
}

// ============ Kernel B: upper-triangle fused GEMM (HMMA) + exp + row/col sums ============
// 128 threads = 4 warps in 2x2 grid, 64x64 warp tile (16 MACs/byte -> crossbar ~75%)
__global__ void __launch_bounds__(128, 2) k_sim() {
    __shared__ __align__(128) char smem[NSTAGE * STAGE_BYTES];  // 48 KB, 3 stages
    const uint32_t sbase = smem_u32(smem);

    const int tid = threadIdx.x;
    const int lane = tid & 31;
    const int wid = tid >> 5;
    const int warp_m = wid & 1;        // 2 warps along M (64 rows each)
    const int warp_n = wid >> 1;       // 2 warps along N (64 cols each)

    // map linear block id -> upper-triangle tile (ti <= tj)
    const int bid = blockIdx.x;
    auto offs = [](int t) { return t * NT - (t * (t - 1)) / 2; };
    int ti = (int)((2.f * NT + 1.f - sqrtf((2.f * NT + 1.f) * (2.f * NT + 1.f) - 8.f * bid)) * 0.5f);
    if (ti < 0) ti = 0;
    if (ti > NT - 1) ti = NT - 1;
    while (offs(ti + 1) <= bid) ti++;
    while (offs(ti) > bid) ti--;
    const int tj = ti + (bid - offs(ti));
    const bool diag = (ti == tj);

    const __nv_bfloat16* za = g_z + (size_t)ti * BM * DIM;
    const __nv_bfloat16* zb = g_z + (size_t)tj * BN * DIM;

    // per-thread load slots: 8 x 16B per stage (A+B = 1024 chunks / 128 thr)
    auto load_stage = [&](int kc) {
        const int st = kc % NSTAGE;
        const uint32_t sA = sbase + st * STAGE_BYTES;
        const uint32_t sB = sA + TILE_BYTES;
#pragma unroll
        for (int it = 0; it < 8; it++) {
            int id = it * 128 + tid;
            int tile = id >> 9;
            int idx = id & 511;
            int row = idx >> 2, ch = idx & 3;
            const __nv_bfloat16* g = (tile ? zb : za) + (size_t)row * DIM + kc * BK + ch * 8;
            cp16((tile ? sB : sA) + swz(row, ch), g);
        }
        asm volatile("cp.async.commit_group;" ::: "memory");
    };

    float acc[4][8][4];
#pragma unroll
    for (int mt = 0; mt < 4; mt++)
#pragma unroll
        for (int nt = 0; nt < 8; nt++)
#pragma unroll
            for (int c = 0; c < 4; c++) acc[mt][nt][c] = 0.f;

    load_stage(0);
    load_stage(1);

    // ldmatrix lane address components
    const int a_row = warp_m * 64 + (lane & 15);
    const int a_chsel = lane >> 4;
    const int b_row = warp_n * 64 + (lane & 7) + ((lane >> 4) << 3);
    const int b_chsel = (lane >> 3) & 1;

    for (int kc = 0; kc < NSTEPS; kc++) {
        asm volatile("cp.async.wait_group 1;" ::: "memory");
        __syncthreads();
        if (kc + NSTAGE - 1 < NSTEPS) load_stage(kc + NSTAGE - 1);  // into buffer freed last iter

        const uint32_t sA = sbase + (kc % NSTAGE) * STAGE_BYTES;
        const uint32_t sB = sA + TILE_BYTES;

#pragma unroll
        for (int ks = 0; ks < 2; ks++) {          // two k16 steps per 32-chunk
            uint32_t a[4][4];
#pragma unroll
            for (int mt = 0; mt < 4; mt++) {
                int row = a_row + mt * 16;
                ldm_x4(a[mt][0], a[mt][1], a[mt][2], a[mt][3],
                       sA + swz(row, ks * 2 + a_chsel));
            }
            // stream B fragments: one ldm.x4 (two n8 frags) -> 8 MMAs -> discard
#pragma unroll
            for (int p = 0; p < 4; p++) {
                int row = b_row + p * 16;
                uint32_t b[4];
                ldm_x4(b[0], b[1], b[2], b[3], sB + swz(row, ks * 2 + b_chsel));
#pragma unroll
                for (int mt = 0; mt < 4; mt++) {
                    mma_16816(acc[mt][p * 2],     a[mt], b);
                    mma_16816(acc[mt][p * 2 + 1], a[mt], b + 2);
                }
            }
        }
    }

    // ---------------- epilogue: exp + per-row (and per-col) sums ----------------
    const int row0 = ti * BM + warp_m * 64 + (lane >> 2);
    const int col0 = tj * BN + warp_n * 64 + (lane & 3) * 2;
    float rs[4][2] = {{0.f,0.f},{0.f,0.f},{0.f,0.f},{0.f,0.f}};   // [mt][rowhalf]

    if (diag) {
        // tile on the diagonal: rows == cols block; mask self-similarity
#pragma unroll
        for (int mt = 0; mt < 4; mt++)
#pragma unroll
            for (int nt = 0; nt < 8; nt++)
#pragma unroll
                for (int c = 0; c < 4; c++) {
                    int grow = row0 + mt * 16 + (c >> 1) * 8;
                    int gcol = col0 + nt * 8 + (c & 1);
                    float e = __expf(acc[mt][nt][c] * INV_TEMP);
                    rs[mt][c >> 1] += (grow == gcol) ? 0.f : e;
                }
    } else {
        // off-diagonal: accumulate row sums AND column sums (symmetry)
        float cs[8][2];
#pragma unroll
        for (int nt = 0; nt < 8; nt++) { cs[nt][0] = 0.f; cs[nt][1] = 0.f; }
#pragma unroll
        for (int mt = 0; mt < 4; mt++)
#pragma unroll
            for (int nt = 0; nt < 8; nt++)
#pragma unroll
                for (int c = 0; c < 4; c++) {
                    float e = __expf(acc[mt][nt][c] * INV_TEMP);
                    rs[mt][c >> 1] += e;
                    cs[nt][c & 1] += e;
                }
        // reduce column sums across the 8 row-groups in the warp (lane bits 2..4)
#pragma unroll
        for (int o = 4; o <= 16; o <<= 1)
#pragma unroll
            for (int nt = 0; nt < 8; nt++) {
                cs[nt][0] += __shfl_xor_sync(0xffffffffu, cs[nt][0], o);
                cs[nt][1] += __shfl_xor_sync(0xffffffffu, cs[nt][1], o);
            }
        if (lane < 4) {
            const int cbase = tj * BN + warp_n * 64 + lane * 2;
#pragma unroll
            for (int nt = 0; nt < 8; nt++) {
                atomicAdd(&g_rowsum[cbase + nt * 8],     cs[nt][0]);
                atomicAdd(&g_rowsum[cbase + nt * 8 + 1], cs[nt][1]);
            }
        }
    }

    // row-sum quad reduce (lanes sharing a row differ only in lane&3)
#pragma unroll
    for (int o = 1; o <= 2; o <<= 1)
#pragma unroll
        for (int mt = 0; mt < 4; mt++)
#pragma unroll
            for (int h = 0; h < 2; h++)
                rs[mt][h] += __shfl_xor_sync(0xffffffffu, rs[mt][h], o);
    if ((lane & 3) == 0) {
#pragma unroll
        for (int mt = 0; mt < 4; mt++)
#pragma unroll
            for (int h = 0; h < 2; h++)
                atomicAdd(&g_rowsum[row0 + mt * 16 + h * 8], rs[mt][h]);
    }
}

// ============ Kernel C: final reduction ============
__global__ void __launch_bounds__(1024) k_red(float* __restrict__ out) {
    __shared__ float sh[1024];
    const int t = threadIdx.x;
    float s = 0.f;
    for (int i = t; i < TWOB; i += 1024) s += logf(g_rowsum[i]);
    float p = 0.f;
    for (int i = t; i < BATCH; i += 1024) p += g_pos[i];
    sh[t] = s - 2.f * INV_TEMP * p;   // sum(lse) - sum(positive logits)
    __syncthreads();
    for (int o = 512; o; o >>= 1) {
        if (t < o) sh[t] += sh[t + o];
        __syncthreads();
    }
    if (!t) out[0] = sh[0] / (float)TWOB;
}

extern "C" void kernel_launch(void* const* d_in, const int* in_sizes, int n_in,
                              void* d_out, int out_size) {
    const float* p1 = (const float*)d_in[0];
    const float* p2 = (const float*)d_in[1];
    k_norm<<<BATCH, 128>>>(p1, p2);
    k_sim<<<NTILES, 128>>>();
    k_red<<<1, 1024>>>((float*)d_out);
}